// round 13
// baseline (speedup 1.0000x reference)
#include <cuda_runtime.h>
#include <cuda_fp16.h>
#include <math.h>
#include <stddef.h>
#include <stdint.h>

#define N_ 50000
#define E_ 600000
#define SB 200     // scan blocks
#define NPB 250    // nodes per scan block (200*250 = 50000)

// ---------------- device scratch (no allocations allowed) -------------------
__device__ int      g_src[E_];
__device__ int      g_dst[E_];
__device__ int      g_esrc[E_];         // CSR: src ids grouped by dst
__device__ int      g_rowstart[N_ + 1]; // CSR offsets
__device__ int      g_deg[N_];
__device__ int      g_fill[N_];
__device__ int      g_chain[SB];        // chained-scan flags: 1+inclusive prefix
__device__ float    g_dinv[N_];
__device__ int      g_flag;             // 1 = edge_index is int64, 0 = int32
__device__ float    g_als[N_ * 2];
__device__ float    g_ald[N_ * 2];
__device__ float    g_va[8 * 128];      // folded attention W@a (rows 0-3: L1, 4-7: L2)
__device__ __half   g_wt[640 * 128];    // all 4 transposed fp16 weights
__device__ __half   g_xh[N_ * 128];     // fp16 copy of input x
__device__ __half   g_bufAh[N_ * 256];  // GEMM outputs fp16
__device__ __half   g_bufCh[N_ * 128];  // activations fp16 (GEMM feed)

// weight row offsets in g_wt
#define WT_G1 0
#define WT_A1 (128 * 128)
#define WT_G2 (384 * 128)
#define WT_A2 (512 * 128)

// ---------------- helpers ---------------------------------------------------
__device__ __forceinline__ float lrelu(float e) { return e > 0.f ? e : 0.2f * e; }

__device__ __forceinline__ float wred_sum(float v) {
#pragma unroll
    for (int o = 16; o; o >>= 1) v += __shfl_xor_sync(0xffffffffu, v, o);
    return v;
}
__device__ __forceinline__ float gred_sum(float v, unsigned m) {
#pragma unroll
    for (int o = 8; o; o >>= 1) v += __shfl_xor_sync(m, v, o);
    return v;
}

__device__ __forceinline__ void ld8(float* v, const __half* p) {
    uint4 u = *(const uint4*)p;
    const __half2* h = (const __half2*)&u;
#pragma unroll
    for (int i = 0; i < 4; i++) {
        float2 f = __half22float2(h[i]);
        v[2 * i] = f.x; v[2 * i + 1] = f.y;
    }
}
__device__ __forceinline__ void st8h(__half* p, const float* v) {
    uint4 u;
    __half2* h = (__half2*)&u;
#pragma unroll
    for (int i = 0; i < 4; i++) h[i] = __floats2half2_rn(v[2 * i], v[2 * i + 1]);
    *(uint4*)p = u;
}
__device__ __forceinline__ uint2 f4_to_h4(float4 v) {
    __half2 h0 = __floats2half2_rn(v.x, v.y);
    __half2 h1 = __floats2half2_rn(v.z, v.w);
    uint2 u;
    u.x = *(unsigned*)&h0; u.y = *(unsigned*)&h1;
    return u;
}
__device__ __forceinline__ uint32_t smem_u32(const void* p) {
    return (uint32_t)__cvta_generic_to_shared(p);
}
__device__ __forceinline__ void ldm4(uint32_t& r0, uint32_t& r1, uint32_t& r2,
                                     uint32_t& r3, uint32_t addr) {
    asm volatile("ldmatrix.sync.aligned.m8n8.x4.shared.b16 {%0,%1,%2,%3}, [%4];"
                 : "=r"(r0), "=r"(r1), "=r"(r2), "=r"(r3) : "r"(addr));
}
__device__ __forceinline__ void mma16816(float* d, const uint32_t* a,
                                         uint32_t b0, uint32_t b1) {
    asm volatile(
        "mma.sync.aligned.m16n8k16.row.col.f32.f16.f16.f32 "
        "{%0,%1,%2,%3}, {%4,%5,%6,%7}, {%8,%9}, {%0,%1,%2,%3};"
        : "+f"(d[0]), "+f"(d[1]), "+f"(d[2]), "+f"(d[3])
        : "r"(a[0]), "r"(a[1]), "r"(a[2]), "r"(a[3]), "r"(b0), "r"(b1));
}

// ---------------- preprocessing ---------------------------------------------
__global__ void k_prep_all(const void* eidx, const float* __restrict__ x,
                           __half* __restrict__ xh) {
    int i = blockIdx.x * 256 + threadIdx.x;
    if (i < N_) g_deg[i] = 0;
    if (i < SB) g_chain[i] = 0;
    if (i < N_ * 32) {
        float4 v = *(const float4*)(x + (size_t)i * 4);
        *(uint2*)(xh + (size_t)i * 4) = f4_to_h4(v);
    }
    if (i == 0) {
        const long long* p = (const long long*)eidx;
        int ok = 1;
        for (int j = 0; j < 128; j++) {
            long long v = p[j];
            if (v < 0 || v >= N_) { ok = 0; break; }
        }
        g_flag = ok;
    }
}

__global__ void k_convert(const void* eidx) {
    int i = blockIdx.x * 256 + threadIdx.x;
    if (i >= E_) return;
    int s, d;
    if (g_flag) {
        const long long* p = (const long long*)eidx;
        s = (int)p[i]; d = (int)p[E_ + i];
    } else {
        const int* p = (const int*)eidx;
        s = p[i]; d = p[E_ + i];
    }
    g_src[i] = s; g_dst[i] = d;
    atomicAdd(&g_deg[d], 1);
}

// single-kernel chained scan: block b publishes (1 + inclusive prefix) in
// g_chain[b]; block b>0 spins on g_chain[b-1]. All SB blocks co-resident.
__global__ void __launch_bounds__(256) k_scan() {
    __shared__ int sh[256];
    __shared__ int base_s;
    int t = threadIdx.x, b = blockIdx.x;
    int i = b * NPB + t;
    int d = (t < NPB) ? g_deg[i] : 0;
    sh[t] = d;
    __syncthreads();
    for (int off = 1; off < 256; off <<= 1) {
        int u = (t >= off) ? sh[t - off] : 0;
        __syncthreads();
        sh[t] += u;
        __syncthreads();
    }
    if (t == 0) {
        int base = 0;
        if (b > 0) {
            int v;
            while ((v = atomicAdd(&g_chain[b - 1], 0)) == 0) {}
            base = v - 1;
        }
        atomicExch(&g_chain[b], base + sh[255] + 1);
        base_s = base;
    }
    __syncthreads();
    if (t < NPB) {
        g_rowstart[i] = base_s + sh[t] - d;  // exclusive prefix
        g_dinv[i] = rsqrtf((float)(d + 1));  // +1 self loop
        g_fill[i] = 0;
    }
    if (b == SB - 1 && t == 0) g_rowstart[N_] = E_;
}

__global__ void k_csr() {
    int i = blockIdx.x * 256 + threadIdx.x;
    if (i >= E_) return;
    int d = g_dst[i];
    int pos = g_rowstart[d] + atomicAdd(&g_fill[d], 1);
    g_esrc[pos] = g_src[i];
}

// ---------------- weight conversions (all 4 matrices, one kernel) -----------
__global__ void k_wcvt_all(const float* __restrict__ Wg1, const float* __restrict__ Wa1,
                           const float* __restrict__ Wg2, const float* __restrict__ Wa2) {
    int idx = blockIdx.x * 256 + threadIdx.x;
    if (idx >= 640 * 128) return;
    int row = idx >> 7, k = idx & 127;
    const float* W; int co, n;
    if (row < 128)      { W = Wg1; co = 128; n = row; }
    else if (row < 384) { W = Wa1; co = 256; n = row - 128; }
    else if (row < 512) { W = Wg2; co = 128; n = row - 384; }
    else                { W = Wa2; co = 128; n = row - 512; }
    g_wt[idx] = __float2half(W[(size_t)k * co + n]);
}

__global__ void k_va_all(const float* __restrict__ Wa1, const float* __restrict__ as1,
                         const float* __restrict__ ad1, const float* __restrict__ Wa2,
                         const float* __restrict__ as2, const float* __restrict__ ad2) {
    int j = blockIdx.x, k = threadIdx.x;
    const float* W; const float* a; int co, C;
    int jj = j & 3;
    if (j < 4) { W = Wa1; a = (jj < 2) ? as1 : ad1; co = 256; C = 128; }
    else       { W = Wa2; a = (jj < 2) ? as2 : ad2; co = 128; C = 64; }
    int h = jj & 1;
    float s = 0.f;
    for (int c = 0; c < C; c++) s += W[(size_t)k * co + h * C + c] * a[h * C + c];
    g_va[j * 128 + k] = s;
}

// ---- HMMA GEMM: BM=128, BN=128, full K=128 resident, dynamic smem 64KB -----
__global__ void __launch_bounds__(256) k_gemm_h(const __half* __restrict__ A,
                                                const __half* __restrict__ Wt,
                                                __half* __restrict__ Ch, int CO) {
    extern __shared__ __half dyn[];
    __half* As = dyn;              // 128x128, row r: granule g at (g ^ (r&7))
    __half* Bs = dyn + 128 * 128;  // 128x128, same swizzle
    const int bm = blockIdx.x * 128, bn = blockIdx.y * 128;
    const int tid = threadIdx.x;
    const int warp = tid >> 5, lane = tid & 31;

    {
        int r = tid >> 1, hh = tid & 1;
        int gr = bm + r;
        const uint4* src = (const uint4*)(A + (size_t)gr * 128 + hh * 64);
        uint4 z = make_uint4(0, 0, 0, 0);
#pragma unroll
        for (int g = 0; g < 8; g++) {
            int gg = hh * 8 + g;
            uint4 v = (gr < N_) ? src[g] : z;
            *(uint4*)&As[r * 128 + ((gg ^ (r & 7)) << 3)] = v;
        }
    }
    {
        int r = tid >> 1, hh = tid & 1;
        const uint4* src = (const uint4*)(Wt + (size_t)(bn + r) * 128 + hh * 64);
#pragma unroll
        for (int g = 0; g < 8; g++) {
            int gg = hh * 8 + g;
            uint4 v = src[g];
            *(uint4*)&Bs[r * 128 + ((gg ^ (r & 7)) << 3)] = v;
        }
    }
    __syncthreads();

    const uint32_t sA = smem_u32(As), sB = smem_u32(Bs);
    const int wm = (warp & 3) * 32, wn = (warp >> 2) * 64;
    float acc[2][8][4];
#pragma unroll
    for (int mt = 0; mt < 2; mt++)
#pragma unroll
        for (int nt = 0; nt < 8; nt++)
#pragma unroll
            for (int i = 0; i < 4; i++) acc[mt][nt][i] = 0.f;

#pragma unroll
    for (int kk = 0; kk < 8; kk++) {
        uint32_t a[2][4];
#pragma unroll
        for (int mt = 0; mt < 2; mt++) {
            int r = wm + mt * 16 + (lane & 15);
            int kg = kk * 2 + (lane >> 4);
            ldm4(a[mt][0], a[mt][1], a[mt][2], a[mt][3],
                 sA + (uint32_t)(r * 128 + ((kg ^ (r & 7)) << 3)) * 2);
        }
        uint32_t b[4][4];
#pragma unroll
        for (int nt2 = 0; nt2 < 4; nt2++) {
            int n = wn + nt2 * 16 + (lane & 7) + ((lane >> 4) << 3);
            int kg = kk * 2 + ((lane >> 3) & 1);
            ldm4(b[nt2][0], b[nt2][1], b[nt2][2], b[nt2][3],
                 sB + (uint32_t)(n * 128 + ((kg ^ (n & 7)) << 3)) * 2);
        }
#pragma unroll
        for (int mt = 0; mt < 2; mt++)
#pragma unroll
            for (int nt = 0; nt < 8; nt++) {
                int nt2 = nt >> 1, sub = nt & 1;
                mma16816(acc[mt][nt], a[mt], b[nt2][sub * 2], b[nt2][sub * 2 + 1]);
            }
    }

#pragma unroll
    for (int mt = 0; mt < 2; mt++) {
        int r0 = bm + wm + mt * 16 + (lane >> 2);
#pragma unroll
        for (int half = 0; half < 2; half++) {
            int r = r0 + half * 8;
            if (r < N_) {
#pragma unroll
                for (int nt = 0; nt < 8; nt++) {
                    int cc = bn + wn + nt * 8 + (lane & 3) * 2;
                    *(__half2*)(Ch + (size_t)r * CO + cc) =
                        __floats2half2_rn(acc[mt][nt][half * 2],
                                          acc[mt][nt][half * 2 + 1]);
                }
            }
        }
    }
}

// ------- GCN aggregate: 2 nodes/warp, 16B loads + BN + ReLU + GAT logits ----
__global__ void __launch_bounds__(256) k_gcn_gather(
    const __half* __restrict__ hh, __half* __restrict__ outh,
    const float* __restrict__ bias, const float* __restrict__ gamma,
    const float* __restrict__ beta, const float* __restrict__ mean,
    const float* __restrict__ var, int vaOff) {
    int gw = (blockIdx.x * 256 + threadIdx.x) >> 5;
    if (gw * 2 >= N_) return;
    int lane = threadIdx.x & 31;
    int g = lane >> 4, cl = lane & 15;
    int n = gw * 2 + g;
    unsigned gmask = 0xFFFFu << (g * 16);
    int cb = cl * 8;

    float din = g_dinv[n];
    float ws = din * din;
    float acc[8];
    ld8(acc, hh + (size_t)n * 128 + cb);
#pragma unroll
    for (int i = 0; i < 8; i++) acc[i] *= ws;

    int beg = g_rowstart[n];
    int deg = g_rowstart[n + 1] - beg;
    for (int base = 0; base < deg; base += 16) {
        int cnt = min(16, deg - base);
        int s = 0; float w = 0.f;
        if (cl < cnt) { s = g_esrc[beg + base + cl]; w = g_dinv[s] * din; }
        for (int j = 0; j < cnt; j++) {
            int sj = __shfl_sync(gmask, s, (g << 4) + j);
            float wj = __shfl_sync(gmask, w, (g << 4) + j);
            float v[8];
            ld8(v, hh + (size_t)sj * 128 + cb);
#pragma unroll
            for (int i = 0; i < 8; i++) acc[i] += wj * v[i];
        }
    }
    float o[8];
    float4 b0 = *(const float4*)(bias + cb),  b1 = *(const float4*)(bias + cb + 4);
    float4 gm0 = *(const float4*)(gamma + cb), gm1 = *(const float4*)(gamma + cb + 4);
    float4 bt0 = *(const float4*)(beta + cb),  bt1 = *(const float4*)(beta + cb + 4);
    float4 mn0 = *(const float4*)(mean + cb),  mn1 = *(const float4*)(mean + cb + 4);
    float4 vr0 = *(const float4*)(var + cb),   vr1 = *(const float4*)(var + cb + 4);
#pragma unroll
    for (int i = 0; i < 8; i++) {
        float bb = (i < 4) ? (&b0.x)[i] : (&b1.x)[i - 4];
        float gg = (i < 4) ? (&gm0.x)[i] : (&gm1.x)[i - 4];
        float tt = (i < 4) ? (&bt0.x)[i] : (&bt1.x)[i - 4];
        float mm = (i < 4) ? (&mn0.x)[i] : (&mn1.x)[i - 4];
        float vv = (i < 4) ? (&vr0.x)[i] : (&vr1.x)[i - 4];
        float val = acc[i] + bb;
        val = (val - mm) * rsqrtf(vv + 1e-5f) * gg + tt;
        o[i] = fmaxf(val, 0.f);
    }
    st8h(outh + (size_t)n * 128 + cb, o);

    float r[4];
#pragma unroll
    for (int j = 0; j < 4; j++) {
        const float* vap = g_va + (vaOff + j) * 128 + cb;
        float4 p0 = *(const float4*)vap, p1 = *(const float4*)(vap + 4);
        float s = o[0] * p0.x + o[1] * p0.y + o[2] * p0.z + o[3] * p0.w +
                  o[4] * p1.x + o[5] * p1.y + o[6] * p1.z + o[7] * p1.w;
        r[j] = gred_sum(s, gmask);
    }
    if (cl == 0) {
        g_als[n * 2 + 0] = r[0]; g_als[n * 2 + 1] = r[1];
        g_ald[n * 2 + 0] = r[2]; g_ald[n * 2 + 1] = r[3];
    }
}

// ------- GAT aggregate, C=128: 1 node/warp, 16B loads cover both heads ------
__global__ void __launch_bounds__(256) k_gat_gather128(
    const __half* __restrict__ hgh, __half* __restrict__ outh,
    const float* __restrict__ bias) {
    int n = (blockIdx.x * 256 + threadIdx.x) >> 5;
    if (n >= N_) return;
    int lane = threadIdx.x & 31;
    int h = lane >> 4;
    int cb = lane * 8;

    float ald0 = g_ald[n * 2], ald1 = g_ald[n * 2 + 1];
    float den0 = __expf(lrelu(g_als[n * 2] + ald0));
    float den1 = __expf(lrelu(g_als[n * 2 + 1] + ald1));
    float wself = h ? den1 : den0;

    float acc[8];
    ld8(acc, hgh + (size_t)n * 256 + cb);
#pragma unroll
    for (int i = 0; i < 8; i++) acc[i] *= wself;

    int beg = g_rowstart[n];
    int deg = g_rowstart[n + 1] - beg;
    for (int base = 0; base < deg; base += 32) {
        int cnt = min(32, deg - base);
        int s = 0; float w0 = 0.f, w1 = 0.f;
        if (lane < cnt) {
            s = g_esrc[beg + base + lane];
            float2 al = *(const float2*)&g_als[2 * s];
            w0 = __expf(lrelu(al.x + ald0));
            w1 = __expf(lrelu(al.y + ald1));
        }
        den0 += wred_sum(w0); den1 += wred_sum(w1);
        for (int j = 0; j < cnt; j++) {
            int sj = __shfl_sync(0xffffffffu, s, j);
            float w0j = __shfl_sync(0xffffffffu, w0, j);
            float w1j = __shfl_sync(0xffffffffu, w1, j);
            float wj = h ? w1j : w0j;
            float v[8];
            ld8(v, hgh + (size_t)sj * 256 + cb);
#pragma unroll
            for (int i = 0; i < 8; i++) acc[i] += wj * v[i];
        }
    }
    float r = 0.5f / (h ? den1 : den0);
    float o[8];
#pragma unroll
    for (int i = 0; i < 8; i++) {
        float val = acc[i] * r;
        o[i] = val + __shfl_xor_sync(0xffffffffu, val, 16);
    }
    if (lane < 16) {
        int oc = lane * 8;
        float4 b0 = *(const float4*)(bias + oc), b1 = *(const float4*)(bias + oc + 4);
#pragma unroll
        for (int i = 0; i < 8; i++) {
            float bb = (i < 4) ? (&b0.x)[i] : (&b1.x)[i - 4];
            o[i] = fmaxf(o[i] + bb, 0.f);
        }
        st8h(outh + (size_t)n * 128 + oc, o);
    }
}

// ------- GAT aggregate, C=64: 2 nodes/warp + bias + log_softmax -------------
__global__ void __launch_bounds__(256) k_gat_gather64(
    const __half* __restrict__ hgh,
    float* __restrict__ out, const float* __restrict__ bias) {
    int gw = (blockIdx.x * 256 + threadIdx.x) >> 5;
    if (gw * 2 >= N_) return;
    int lane = threadIdx.x & 31;
    int g = lane >> 4, cl = lane & 15;
    int n = gw * 2 + g;
    unsigned gmask = 0xFFFFu << (g * 16);
    int h = cl >> 3;
    int cb = (cl & 7) * 8;

    float ald0 = g_ald[n * 2], ald1 = g_ald[n * 2 + 1];
    float es0 = __expf(lrelu(g_als[n * 2] + ald0));
    float es1 = __expf(lrelu(g_als[n * 2 + 1] + ald1));
    float den = h ? es1 : es0;

    float acc[8];
    ld8(acc, hgh + (size_t)n * 128 + cl * 8);
#pragma unroll
    for (int i = 0; i < 8; i++) acc[i] *= den;

    int beg = g_rowstart[n];
    int deg = g_rowstart[n + 1] - beg;
    for (int base = 0; base < deg; base += 16) {
        int cnt = min(16, deg - base);
        int s = 0; float w0 = 0.f, w1 = 0.f;
        if (cl < cnt) {
            s = g_esrc[beg + base + cl];
            float2 al = *(const float2*)&g_als[2 * s];
            w0 = __expf(lrelu(al.x + ald0));
            w1 = __expf(lrelu(al.y + ald1));
        }
        float sw0 = gred_sum(w0, gmask), sw1 = gred_sum(w1, gmask);
        den += h ? sw1 : sw0;
        for (int j = 0; j < cnt; j++) {
            int sj = __shfl_sync(gmask, s, (g << 4) + j);
            float w0j = __shfl_sync(gmask, w0, (g << 4) + j);
            float w1j = __shfl_sync(gmask, w1, (g << 4) + j);
            float wj = h ? w1j : w0j;
            float v[8];
            ld8(v, hgh + (size_t)sj * 128 + cl * 8);
#pragma unroll
            for (int i = 0; i < 8; i++) acc[i] += wj * v[i];
        }
    }
    float inv = 1.f / den;
    float4 b0 = *(const float4*)(bias + cb), b1 = *(const float4*)(bias + cb + 4);
    float o[8];
#pragma unroll
    for (int i = 0; i < 8; i++) {
        float val = acc[i] * inv;
        float bb = (i < 4) ? (&b0.x)[i] : (&b1.x)[i - 4];
        o[i] = 0.5f * (val + __shfl_xor_sync(gmask, val, 8)) + bb;
    }
    float lm = o[0];
#pragma unroll
    for (int i = 1; i < 8; i++) lm = fmaxf(lm, o[i]);
#pragma unroll
    for (int off = 4; off; off >>= 1) lm = fmaxf(lm, __shfl_xor_sync(gmask, lm, off));
    float sum = 0.f;
#pragma unroll
    for (int i = 0; i < 8; i++) sum += __expf(o[i] - lm);
#pragma unroll
    for (int off = 4; off; off >>= 1) sum += __shfl_xor_sync(gmask, sum, off);
    float l = lm + logf(sum);
    if (h == 0) {
        float* op = out + (size_t)n * 64 + cb;
        *(float4*)op = make_float4(o[0] - l, o[1] - l, o[2] - l, o[3] - l);
        *(float4*)(op + 4) = make_float4(o[4] - l, o[5] - l, o[6] - l, o[7] - l);
    }
}

// ---------------- launch -----------------------------------------------------
extern "C" void kernel_launch(void* const* d_in, const int* in_sizes, int n_in,
                              void* d_out, int out_size) {
    const float* x   = (const float*)d_in[0];
    const void*  ei  = d_in[1];
    const float* Wg1 = (const float*)d_in[2];
    const float* bg1 = (const float*)d_in[3];
    const float* g1g = (const float*)d_in[4];
    const float* g1b = (const float*)d_in[5];
    const float* g1m = (const float*)d_in[6];
    const float* g1v = (const float*)d_in[7];
    const float* Wa1 = (const float*)d_in[8];
    const float* as1 = (const float*)d_in[9];
    const float* ad1 = (const float*)d_in[10];
    const float* ba1 = (const float*)d_in[11];
    const float* Wg2 = (const float*)d_in[12];
    const float* bg2 = (const float*)d_in[13];
    const float* g2g = (const float*)d_in[14];
    const float* g2b = (const float*)d_in[15];
    const float* g2m = (const float*)d_in[16];
    const float* g2v = (const float*)d_in[17];
    const float* Wa2 = (const float*)d_in[18];
    const float* as2 = (const float*)d_in[19];
    const float* ad2 = (const float*)d_in[20];
    const float* ba2 = (const float*)d_in[21];
    float* out = (float*)d_out;

    __half *bufAh, *bufCh, *wt, *xh;
    cudaGetSymbolAddress((void**)&bufAh, g_bufAh);
    cudaGetSymbolAddress((void**)&bufCh, g_bufCh);
    cudaGetSymbolAddress((void**)&wt, g_wt);
    cudaGetSymbolAddress((void**)&xh, g_xh);

    const int GEMM_SMEM = 2 * 128 * 128 * (int)sizeof(__half);  // 64 KB
    static int attr_done = 0;
    if (!attr_done) {
        cudaFuncSetAttribute(k_gemm_h, cudaFuncAttributeMaxDynamicSharedMemorySize,
                             GEMM_SMEM);
        attr_done = 1;
    }

    const int TB = 256;
    const int eb = (E_ + TB - 1) / TB;
    const int nw1 = (N_ * 32 + TB - 1) / TB;        // 1 node/warp grids
    const int nw2 = ((N_ / 2) * 32 + TB - 1) / TB;  // 2 nodes/warp grids
    const int GX = (N_ + 127) / 128;                // 391 GEMM row tiles

    // ---- preprocessing
    k_prep_all<<<(N_ * 32 + TB - 1) / TB, TB>>>(ei, x, xh);
    k_convert<<<eb, TB>>>(ei);
    k_scan<<<SB, TB>>>();
    k_csr<<<eb, TB>>>();
    k_wcvt_all<<<(640 * 128) / TB, TB>>>(Wg1, Wa1, Wg2, Wa2);
    k_va_all<<<8, 128>>>(Wa1, as1, ad1, Wa2, as2, ad2);

    // ---- GCN1 (+ bias + BN1 + ReLU + GAT1 logits)
    k_gemm_h<<<dim3(GX, 1), TB, GEMM_SMEM>>>(xh, wt + WT_G1, bufAh, 128);
    k_gcn_gather<<<nw2, TB>>>(bufAh, bufCh, bg1, g1g, g1b, g1m, g1v, 0);

    // ---- GAT1 (single-pass softmax + head-mean + bias + ReLU)
    k_gemm_h<<<dim3(GX, 2), TB, GEMM_SMEM>>>(bufCh, wt + WT_A1, bufAh, 256);
    k_gat_gather128<<<nw1, TB>>>(bufAh, bufCh, ba1);

    // ---- GCN2 (+ bias + BN2 + ReLU + GAT2 logits)
    k_gemm_h<<<dim3(GX, 1), TB, GEMM_SMEM>>>(bufCh, wt + WT_G2, bufAh, 128);
    k_gcn_gather<<<nw2, TB>>>(bufAh, bufCh, bg2, g2g, g2b, g2m, g2v, 4);

    // ---- GAT2 (single-pass softmax + head-mean + bias + log_softmax)
    k_gemm_h<<<dim3(GX, 1), TB, GEMM_SMEM>>>(bufCh, wt + WT_A2, bufAh, 128);
    k_gat_gather64<<<nw2, TB>>>(bufAh, out, ba2);
}

// round 14
// speedup vs baseline: 1.4049x; 1.4049x over previous
#include <cuda_runtime.h>
#include <cuda_fp16.h>
#include <math.h>
#include <stddef.h>
#include <stdint.h>

#define N_ 50000
#define E_ 600000
#define SB 200     // scan blocks
#define NPB 250    // nodes per scan block (200*250 = 50000)

// ---------------- device scratch (no allocations allowed) -------------------
__device__ int      g_src[E_];
__device__ int      g_dst[E_];
__device__ int      g_esrc[E_];         // CSR: src ids grouped by dst
__device__ int      g_rowstart[N_ + 1]; // CSR offsets
__device__ int      g_deg[N_];
__device__ int      g_fill[N_];
__device__ int      g_bsum[SB];
__device__ int      g_bpre[SB];
__device__ float    g_dinv[N_];
__device__ int      g_flag;             // 1 = edge_index is int64, 0 = int32
__device__ float    g_als[N_ * 2];
__device__ float    g_ald[N_ * 2];
__device__ float    g_va[8 * 128];      // folded attention W@a (rows 0-3: L1, 4-7: L2)
__device__ __half   g_wt[640 * 128];    // all 4 transposed fp16 weights
__device__ __half   g_xh[N_ * 128];     // fp16 copy of input x
__device__ __half   g_bufAh[N_ * 256];  // GEMM outputs fp16
__device__ __half   g_bufCh[N_ * 128];  // activations fp16 (GEMM feed)

// weight row offsets in g_wt
#define WT_G1 0
#define WT_A1 (128 * 128)
#define WT_G2 (384 * 128)
#define WT_A2 (512 * 128)

// ---------------- helpers ---------------------------------------------------
__device__ __forceinline__ float lrelu(float e) { return e > 0.f ? e : 0.2f * e; }

__device__ __forceinline__ float wred_sum(float v) {
#pragma unroll
    for (int o = 16; o; o >>= 1) v += __shfl_xor_sync(0xffffffffu, v, o);
    return v;
}
__device__ __forceinline__ float gred_sum(float v, unsigned m) {
#pragma unroll
    for (int o = 8; o; o >>= 1) v += __shfl_xor_sync(m, v, o);
    return v;
}

__device__ __forceinline__ void ld8(float* v, const __half* p) {
    uint4 u = *(const uint4*)p;
    const __half2* h = (const __half2*)&u;
#pragma unroll
    for (int i = 0; i < 4; i++) {
        float2 f = __half22float2(h[i]);
        v[2 * i] = f.x; v[2 * i + 1] = f.y;
    }
}
__device__ __forceinline__ void st8h(__half* p, const float* v) {
    uint4 u;
    __half2* h = (__half2*)&u;
#pragma unroll
    for (int i = 0; i < 4; i++) h[i] = __floats2half2_rn(v[2 * i], v[2 * i + 1]);
    *(uint4*)p = u;
}
__device__ __forceinline__ uint2 f4_to_h4(float4 v) {
    __half2 h0 = __floats2half2_rn(v.x, v.y);
    __half2 h1 = __floats2half2_rn(v.z, v.w);
    uint2 u;
    u.x = *(unsigned*)&h0; u.y = *(unsigned*)&h1;
    return u;
}
__device__ __forceinline__ uint32_t smem_u32(const void* p) {
    return (uint32_t)__cvta_generic_to_shared(p);
}
__device__ __forceinline__ void ldm4(uint32_t& r0, uint32_t& r1, uint32_t& r2,
                                     uint32_t& r3, uint32_t addr) {
    asm volatile("ldmatrix.sync.aligned.m8n8.x4.shared.b16 {%0,%1,%2,%3}, [%4];"
                 : "=r"(r0), "=r"(r1), "=r"(r2), "=r"(r3) : "r"(addr));
}
__device__ __forceinline__ void mma16816(float* d, const uint32_t* a,
                                         uint32_t b0, uint32_t b1) {
    asm volatile(
        "mma.sync.aligned.m16n8k16.row.col.f32.f16.f16.f32 "
        "{%0,%1,%2,%3}, {%4,%5,%6,%7}, {%8,%9}, {%0,%1,%2,%3};"
        : "+f"(d[0]), "+f"(d[1]), "+f"(d[2]), "+f"(d[3])
        : "r"(a[0]), "r"(a[1]), "r"(a[2]), "r"(a[3]), "r"(b0), "r"(b1));
}

// ---------------- preprocessing ---------------------------------------------
__global__ void k_prep_all(const void* eidx, const float* __restrict__ x,
                           __half* __restrict__ xh) {
    int i = blockIdx.x * 256 + threadIdx.x;
    if (i < N_) g_deg[i] = 0;
    if (i < N_ * 32) {
        float4 v = *(const float4*)(x + (size_t)i * 4);
        *(uint2*)(xh + (size_t)i * 4) = f4_to_h4(v);
    }
    if (i == 0) {
        const long long* p = (const long long*)eidx;
        int ok = 1;
        for (int j = 0; j < 128; j++) {
            long long v = p[j];
            if (v < 0 || v >= N_) { ok = 0; break; }
        }
        g_flag = ok;
    }
}

__global__ void k_convert(const void* eidx) {
    int i = blockIdx.x * 256 + threadIdx.x;
    if (i >= E_) return;
    int s, d;
    if (g_flag) {
        const long long* p = (const long long*)eidx;
        s = (int)p[i]; d = (int)p[E_ + i];
    } else {
        const int* p = (const int*)eidx;
        s = p[i]; d = p[E_ + i];
    }
    g_src[i] = s; g_dst[i] = d;
    atomicAdd(&g_deg[d], 1);
}

__global__ void __launch_bounds__(256) k_scan1() {
    __shared__ int sh[256];
    int t = threadIdx.x, b = blockIdx.x;
    int i = b * NPB + t;
    sh[t] = (t < NPB) ? g_deg[i] : 0;
    __syncthreads();
    for (int off = 128; off; off >>= 1) {
        if (t < off) sh[t] += sh[t + off];
        __syncthreads();
    }
    if (t == 0) g_bsum[b] = sh[0];
}

__global__ void __launch_bounds__(256) k_scan2() {
    __shared__ int sh[256];
    int t = threadIdx.x;
    int v = (t < SB) ? g_bsum[t] : 0;
    sh[t] = v;
    __syncthreads();
    for (int off = 1; off < 256; off <<= 1) {
        int u = (t >= off) ? sh[t - off] : 0;
        __syncthreads();
        sh[t] += u;
        __syncthreads();
    }
    if (t < SB) g_bpre[t] = sh[t] - v;  // exclusive
}

__global__ void __launch_bounds__(256) k_scan3() {
    __shared__ int sh[256];
    int t = threadIdx.x, b = blockIdx.x;
    int i = b * NPB + t;
    int d = (t < NPB) ? g_deg[i] : 0;
    sh[t] = d;
    __syncthreads();
    for (int off = 1; off < 256; off <<= 1) {
        int u = (t >= off) ? sh[t - off] : 0;
        __syncthreads();
        sh[t] += u;
        __syncthreads();
    }
    if (t < NPB) {
        g_rowstart[i] = g_bpre[b] + sh[t] - d;
        g_dinv[i] = rsqrtf((float)(d + 1));  // +1 self loop
        g_fill[i] = 0;
    }
    if (b == SB - 1 && t == 0) g_rowstart[N_] = E_;
}

__global__ void k_csr() {
    int i = blockIdx.x * 256 + threadIdx.x;
    if (i >= E_) return;
    int d = g_dst[i];
    int pos = g_rowstart[d] + atomicAdd(&g_fill[d], 1);
    g_esrc[pos] = g_src[i];
}

// ------- constants: weight transpose-convert + folded attention (1 kernel) --
__global__ void k_const(const float* __restrict__ Wg1, const float* __restrict__ Wa1,
                        const float* __restrict__ Wg2, const float* __restrict__ Wa2,
                        const float* __restrict__ as1, const float* __restrict__ ad1,
                        const float* __restrict__ as2, const float* __restrict__ ad2) {
    int b = blockIdx.x;
    if (b < 320) {  // weight convert: 640*128 elems = 320 blocks * 256
        int idx = b * 256 + threadIdx.x;
        int row = idx >> 7, k = idx & 127;
        const float* W; int co, n;
        if (row < 128)      { W = Wg1; co = 128; n = row; }
        else if (row < 384) { W = Wa1; co = 256; n = row - 128; }
        else if (row < 512) { W = Wg2; co = 128; n = row - 384; }
        else                { W = Wa2; co = 128; n = row - 512; }
        g_wt[idx] = __float2half(W[(size_t)k * co + n]);
    } else {        // folded attention vectors: 8 blocks
        int j = b - 320, k = threadIdx.x;
        if (k < 128) {
            const float* W; const float* a; int co, C;
            int jj = j & 3;
            if (j < 4) { W = Wa1; a = (jj < 2) ? as1 : ad1; co = 256; C = 128; }
            else       { W = Wa2; a = (jj < 2) ? as2 : ad2; co = 128; C = 64; }
            int h = jj & 1;
            float s = 0.f;
            for (int c = 0; c < C; c++) s += W[(size_t)k * co + h * C + c] * a[h * C + c];
            g_va[j * 128 + k] = s;
        }
    }
}

// ---- HMMA GEMM: BM=128, BN=64 x (CO/64 sequential halves reusing As) -------
// 48KB static smem, 32 accumulators/thread (R12 occupancy), A read ONCE/block.
__global__ void __launch_bounds__(256) k_gemm_h(const __half* __restrict__ A,
                                                const __half* __restrict__ Wt,
                                                __half* __restrict__ Ch, int CO) {
    __shared__ __half As[128 * 128];  // row r: granule g stored at (g ^ (r&7))
    __shared__ __half Bs[64 * 128];
    const int bm = blockIdx.x * 128;
    const int tid = threadIdx.x;
    const int warp = tid >> 5, lane = tid & 31;

    // load A tile once (rows bm..bm+127, all K)
    {
        int r = tid >> 1, hh = tid & 1;
        int gr = bm + r;
        const uint4* src = (const uint4*)(A + (size_t)gr * 128 + hh * 64);
        uint4 z = make_uint4(0, 0, 0, 0);
#pragma unroll
        for (int g = 0; g < 8; g++) {
            int gg = hh * 8 + g;
            uint4 v = (gr < N_) ? src[g] : z;
            *(uint4*)&As[r * 128 + ((gg ^ (r & 7)) << 3)] = v;
        }
    }

    const uint32_t sA = smem_u32(As), sB = smem_u32(Bs);
    const int wm = (warp & 3) * 32, wn = (warp >> 2) * 32;
    const int H = CO >> 6;  // 64-col halves

    for (int hb = 0; hb < H; hb++) {
        __syncthreads();  // As visible (iter 0) / prior ldmatrix of Bs done
        // load B tile for cols [hb*64, hb*64+64)
        {
            int n = tid >> 2, q = tid & 3;
            const uint4* src = (const uint4*)(Wt + (size_t)(hb * 64 + n) * 128 + q * 32);
#pragma unroll
            for (int g = 0; g < 4; g++) {
                int gg = q * 4 + g;
                uint4 v = src[g];
                *(uint4*)&Bs[n * 128 + ((gg ^ (n & 7)) << 3)] = v;
            }
        }
        __syncthreads();

        float acc[2][4][4];
#pragma unroll
        for (int mt = 0; mt < 2; mt++)
#pragma unroll
            for (int nt = 0; nt < 4; nt++)
#pragma unroll
                for (int i = 0; i < 4; i++) acc[mt][nt][i] = 0.f;

#pragma unroll
        for (int kk = 0; kk < 8; kk++) {
            uint32_t a[2][4];
#pragma unroll
            for (int mt = 0; mt < 2; mt++) {
                int r = wm + mt * 16 + (lane & 15);
                int kg = kk * 2 + (lane >> 4);
                ldm4(a[mt][0], a[mt][1], a[mt][2], a[mt][3],
                     sA + (uint32_t)(r * 128 + ((kg ^ (r & 7)) << 3)) * 2);
            }
            uint32_t b[2][4];
#pragma unroll
            for (int nt2 = 0; nt2 < 2; nt2++) {
                int n = wn + nt2 * 16 + (lane & 7) + ((lane >> 4) << 3);
                int kg = kk * 2 + ((lane >> 3) & 1);
                ldm4(b[nt2][0], b[nt2][1], b[nt2][2], b[nt2][3],
                     sB + (uint32_t)(n * 128 + ((kg ^ (n & 7)) << 3)) * 2);
            }
#pragma unroll
            for (int mt = 0; mt < 2; mt++)
#pragma unroll
                for (int nt = 0; nt < 4; nt++) {
                    int nt2 = nt >> 1, sub = nt & 1;
                    mma16816(acc[mt][nt], a[mt], b[nt2][sub * 2], b[nt2][sub * 2 + 1]);
                }
        }

        int bn = hb * 64;
#pragma unroll
        for (int mt = 0; mt < 2; mt++) {
            int r0 = bm + wm + mt * 16 + (lane >> 2);
#pragma unroll
            for (int half = 0; half < 2; half++) {
                int r = r0 + half * 8;
                if (r < N_) {
#pragma unroll
                    for (int nt = 0; nt < 4; nt++) {
                        int cc = bn + wn + nt * 8 + (lane & 3) * 2;
                        *(__half2*)(Ch + (size_t)r * CO + cc) =
                            __floats2half2_rn(acc[mt][nt][half * 2],
                                              acc[mt][nt][half * 2 + 1]);
                    }
                }
            }
        }
    }
}

// ------- GCN aggregate: 2 nodes/warp, 16B loads + BN + ReLU + GAT logits ----
__global__ void __launch_bounds__(256) k_gcn_gather(
    const __half* __restrict__ hh, __half* __restrict__ outh,
    const float* __restrict__ bias, const float* __restrict__ gamma,
    const float* __restrict__ beta, const float* __restrict__ mean,
    const float* __restrict__ var, int vaOff) {
    int gw = (blockIdx.x * 256 + threadIdx.x) >> 5;
    if (gw * 2 >= N_) return;
    int lane = threadIdx.x & 31;
    int g = lane >> 4, cl = lane & 15;
    int n = gw * 2 + g;
    unsigned gmask = 0xFFFFu << (g * 16);
    int cb = cl * 8;

    float din = g_dinv[n];
    float ws = din * din;
    float acc[8];
    ld8(acc, hh + (size_t)n * 128 + cb);
#pragma unroll
    for (int i = 0; i < 8; i++) acc[i] *= ws;

    int beg = g_rowstart[n];
    int deg = g_rowstart[n + 1] - beg;
    for (int base = 0; base < deg; base += 16) {
        int cnt = min(16, deg - base);
        int s = 0; float w = 0.f;
        if (cl < cnt) { s = g_esrc[beg + base + cl]; w = g_dinv[s] * din; }
        for (int j = 0; j < cnt; j++) {
            int sj = __shfl_sync(gmask, s, (g << 4) + j);
            float wj = __shfl_sync(gmask, w, (g << 4) + j);
            float v[8];
            ld8(v, hh + (size_t)sj * 128 + cb);
#pragma unroll
            for (int i = 0; i < 8; i++) acc[i] += wj * v[i];
        }
    }
    float o[8];
    float4 b0 = *(const float4*)(bias + cb),  b1 = *(const float4*)(bias + cb + 4);
    float4 gm0 = *(const float4*)(gamma + cb), gm1 = *(const float4*)(gamma + cb + 4);
    float4 bt0 = *(const float4*)(beta + cb),  bt1 = *(const float4*)(beta + cb + 4);
    float4 mn0 = *(const float4*)(mean + cb),  mn1 = *(const float4*)(mean + cb + 4);
    float4 vr0 = *(const float4*)(var + cb),   vr1 = *(const float4*)(var + cb + 4);
#pragma unroll
    for (int i = 0; i < 8; i++) {
        float bb = (i < 4) ? (&b0.x)[i] : (&b1.x)[i - 4];
        float gg = (i < 4) ? (&gm0.x)[i] : (&gm1.x)[i - 4];
        float tt = (i < 4) ? (&bt0.x)[i] : (&bt1.x)[i - 4];
        float mm = (i < 4) ? (&mn0.x)[i] : (&mn1.x)[i - 4];
        float vv = (i < 4) ? (&vr0.x)[i] : (&vr1.x)[i - 4];
        float val = acc[i] + bb;
        val = (val - mm) * rsqrtf(vv + 1e-5f) * gg + tt;
        o[i] = fmaxf(val, 0.f);
    }
    st8h(outh + (size_t)n * 128 + cb, o);

    float r[4];
#pragma unroll
    for (int j = 0; j < 4; j++) {
        const float* vap = g_va + (vaOff + j) * 128 + cb;
        float4 p0 = *(const float4*)vap, p1 = *(const float4*)(vap + 4);
        float s = o[0] * p0.x + o[1] * p0.y + o[2] * p0.z + o[3] * p0.w +
                  o[4] * p1.x + o[5] * p1.y + o[6] * p1.z + o[7] * p1.w;
        r[j] = gred_sum(s, gmask);
    }
    if (cl == 0) {
        g_als[n * 2 + 0] = r[0]; g_als[n * 2 + 1] = r[1];
        g_ald[n * 2 + 0] = r[2]; g_ald[n * 2 + 1] = r[3];
    }
}

// ------- GAT aggregate, C=128: 1 node/warp, 16B loads cover both heads ------
__global__ void __launch_bounds__(256) k_gat_gather128(
    const __half* __restrict__ hgh, __half* __restrict__ outh,
    const float* __restrict__ bias) {
    int n = (blockIdx.x * 256 + threadIdx.x) >> 5;
    if (n >= N_) return;
    int lane = threadIdx.x & 31;
    int h = lane >> 4;
    int cb = lane * 8;

    float ald0 = g_ald[n * 2], ald1 = g_ald[n * 2 + 1];
    float den0 = __expf(lrelu(g_als[n * 2] + ald0));
    float den1 = __expf(lrelu(g_als[n * 2 + 1] + ald1));
    float wself = h ? den1 : den0;

    float acc[8];
    ld8(acc, hgh + (size_t)n * 256 + cb);
#pragma unroll
    for (int i = 0; i < 8; i++) acc[i] *= wself;

    int beg = g_rowstart[n];
    int deg = g_rowstart[n + 1] - beg;
    for (int base = 0; base < deg; base += 32) {
        int cnt = min(32, deg - base);
        int s = 0; float w0 = 0.f, w1 = 0.f;
        if (lane < cnt) {
            s = g_esrc[beg + base + lane];
            float2 al = *(const float2*)&g_als[2 * s];
            w0 = __expf(lrelu(al.x + ald0));
            w1 = __expf(lrelu(al.y + ald1));
        }
        den0 += wred_sum(w0); den1 += wred_sum(w1);
        for (int j = 0; j < cnt; j++) {
            int sj = __shfl_sync(0xffffffffu, s, j);
            float w0j = __shfl_sync(0xffffffffu, w0, j);
            float w1j = __shfl_sync(0xffffffffu, w1, j);
            float wj = h ? w1j : w0j;
            float v[8];
            ld8(v, hgh + (size_t)sj * 256 + cb);
#pragma unroll
            for (int i = 0; i < 8; i++) acc[i] += wj * v[i];
        }
    }
    float r = 0.5f / (h ? den1 : den0);
    float o[8];
#pragma unroll
    for (int i = 0; i < 8; i++) {
        float val = acc[i] * r;
        o[i] = val + __shfl_xor_sync(0xffffffffu, val, 16);
    }
    if (lane < 16) {
        int oc = lane * 8;
        float4 b0 = *(const float4*)(bias + oc), b1 = *(const float4*)(bias + oc + 4);
#pragma unroll
        for (int i = 0; i < 8; i++) {
            float bb = (i < 4) ? (&b0.x)[i] : (&b1.x)[i - 4];
            o[i] = fmaxf(o[i] + bb, 0.f);
        }
        st8h(outh + (size_t)n * 128 + oc, o);
    }
}

// ------- GAT aggregate, C=64: 2 nodes/warp + bias + log_softmax -------------
__global__ void __launch_bounds__(256) k_gat_gather64(
    const __half* __restrict__ hgh,
    float* __restrict__ out, const float* __restrict__ bias) {
    int gw = (blockIdx.x * 256 + threadIdx.x) >> 5;
    if (gw * 2 >= N_) return;
    int lane = threadIdx.x & 31;
    int g = lane >> 4, cl = lane & 15;
    int n = gw * 2 + g;
    unsigned gmask = 0xFFFFu << (g * 16);
    int h = cl >> 3;
    int cb = (cl & 7) * 8;

    float ald0 = g_ald[n * 2], ald1 = g_ald[n * 2 + 1];
    float es0 = __expf(lrelu(g_als[n * 2] + ald0));
    float es1 = __expf(lrelu(g_als[n * 2 + 1] + ald1));
    float den = h ? es1 : es0;

    float acc[8];
    ld8(acc, hgh + (size_t)n * 128 + cl * 8);
#pragma unroll
    for (int i = 0; i < 8; i++) acc[i] *= den;

    int beg = g_rowstart[n];
    int deg = g_rowstart[n + 1] - beg;
    for (int base = 0; base < deg; base += 16) {
        int cnt = min(16, deg - base);
        int s = 0; float w0 = 0.f, w1 = 0.f;
        if (cl < cnt) {
            s = g_esrc[beg + base + cl];
            float2 al = *(const float2*)&g_als[2 * s];
            w0 = __expf(lrelu(al.x + ald0));
            w1 = __expf(lrelu(al.y + ald1));
        }
        float sw0 = gred_sum(w0, gmask), sw1 = gred_sum(w1, gmask);
        den += h ? sw1 : sw0;
        for (int j = 0; j < cnt; j++) {
            int sj = __shfl_sync(gmask, s, (g << 4) + j);
            float w0j = __shfl_sync(gmask, w0, (g << 4) + j);
            float w1j = __shfl_sync(gmask, w1, (g << 4) + j);
            float wj = h ? w1j : w0j;
            float v[8];
            ld8(v, hgh + (size_t)sj * 128 + cl * 8);
#pragma unroll
            for (int i = 0; i < 8; i++) acc[i] += wj * v[i];
        }
    }
    float inv = 1.f / den;
    float4 b0 = *(const float4*)(bias + cb), b1 = *(const float4*)(bias + cb + 4);
    float o[8];
#pragma unroll
    for (int i = 0; i < 8; i++) {
        float val = acc[i] * inv;
        float bb = (i < 4) ? (&b0.x)[i] : (&b1.x)[i - 4];
        o[i] = 0.5f * (val + __shfl_xor_sync(gmask, val, 8)) + bb;
    }
    float lm = o[0];
#pragma unroll
    for (int i = 1; i < 8; i++) lm = fmaxf(lm, o[i]);
#pragma unroll
    for (int off = 4; off; off >>= 1) lm = fmaxf(lm, __shfl_xor_sync(gmask, lm, off));
    float sum = 0.f;
#pragma unroll
    for (int i = 0; i < 8; i++) sum += __expf(o[i] - lm);
#pragma unroll
    for (int off = 4; off; off >>= 1) sum += __shfl_xor_sync(gmask, sum, off);
    float l = lm + logf(sum);
    if (h == 0) {
        float* op = out + (size_t)n * 64 + cb;
        *(float4*)op = make_float4(o[0] - l, o[1] - l, o[2] - l, o[3] - l);
        *(float4*)(op + 4) = make_float4(o[4] - l, o[5] - l, o[6] - l, o[7] - l);
    }
}

// ---------------- launch -----------------------------------------------------
extern "C" void kernel_launch(void* const* d_in, const int* in_sizes, int n_in,
                              void* d_out, int out_size) {
    const float* x   = (const float*)d_in[0];
    const void*  ei  = d_in[1];
    const float* Wg1 = (const float*)d_in[2];
    const float* bg1 = (const float*)d_in[3];
    const float* g1g = (const float*)d_in[4];
    const float* g1b = (const float*)d_in[5];
    const float* g1m = (const float*)d_in[6];
    const float* g1v = (const float*)d_in[7];
    const float* Wa1 = (const float*)d_in[8];
    const float* as1 = (const float*)d_in[9];
    const float* ad1 = (const float*)d_in[10];
    const float* ba1 = (const float*)d_in[11];
    const float* Wg2 = (const float*)d_in[12];
    const float* bg2 = (const float*)d_in[13];
    const float* g2g = (const float*)d_in[14];
    const float* g2b = (const float*)d_in[15];
    const float* g2m = (const float*)d_in[16];
    const float* g2v = (const float*)d_in[17];
    const float* Wa2 = (const float*)d_in[18];
    const float* as2 = (const float*)d_in[19];
    const float* ad2 = (const float*)d_in[20];
    const float* ba2 = (const float*)d_in[21];
    float* out = (float*)d_out;

    __half *bufAh, *bufCh, *wt, *xh;
    cudaGetSymbolAddress((void**)&bufAh, g_bufAh);
    cudaGetSymbolAddress((void**)&bufCh, g_bufCh);
    cudaGetSymbolAddress((void**)&wt, g_wt);
    cudaGetSymbolAddress((void**)&xh, g_xh);

    const int TB = 256;
    const int eb = (E_ + TB - 1) / TB;
    const int nw1 = (N_ * 32 + TB - 1) / TB;        // 1 node/warp grids
    const int nw2 = ((N_ / 2) * 32 + TB - 1) / TB;  // 2 nodes/warp grids
    const int GX = (N_ + 127) / 128;                // 391 GEMM row tiles

    // ---- preprocessing
    k_prep_all<<<(N_ * 32 + TB - 1) / TB, TB>>>(ei, x, xh);
    k_convert<<<eb, TB>>>(ei);
    k_scan1<<<SB, TB>>>();
    k_scan2<<<1, TB>>>();
    k_scan3<<<SB, TB>>>();
    k_csr<<<eb, TB>>>();
    k_const<<<328, TB>>>(Wg1, Wa1, Wg2, Wa2, as1, ad1, as2, ad2);

    // ---- GCN1 (+ bias + BN1 + ReLU + GAT1 logits)
    k_gemm_h<<<GX, TB>>>(xh, wt + WT_G1, bufAh, 128);
    k_gcn_gather<<<nw2, TB>>>(bufAh, bufCh, bg1, g1g, g1b, g1m, g1v, 0);

    // ---- GAT1 (single-pass softmax + head-mean + bias + ReLU)
    k_gemm_h<<<GX, TB>>>(bufCh, wt + WT_A1, bufAh, 256);
    k_gat_gather128<<<nw1, TB>>>(bufAh, bufCh, ba1);

    // ---- GCN2 (+ bias + BN2 + ReLU + GAT2 logits)
    k_gemm_h<<<GX, TB>>>(bufCh, wt + WT_G2, bufAh, 128);
    k_gcn_gather<<<nw2, TB>>>(bufAh, bufCh, bg2, g2g, g2b, g2m, g2v, 4);

    // ---- GAT2 (single-pass softmax + head-mean + bias + log_softmax)
    k_gemm_h<<<GX, TB>>>(bufCh, wt + WT_A2, bufAh, 128);
    k_gat_gather64<<<nw2, TB>>>(bufAh, out, ba2);
}

// round 17
// speedup vs baseline: 1.4170x; 1.0086x over previous
#include <cuda_runtime.h>
#include <cuda_fp16.h>
#include <math.h>
#include <stddef.h>
#include <stdint.h>

#define N_ 50000
#define E_ 600000
#define SB 200     // scan blocks
#define NPB 250    // nodes per scan block (200*250 = 50000)

// ---------------- device scratch (no allocations allowed) -------------------
__device__ int      g_esrc[E_];         // CSR: src ids grouped by dst
__device__ int      g_rowstart[N_ + 1]; // CSR offsets
__device__ int      g_deg[N_];
__device__ int      g_fill[N_];
__device__ int      g_bsum[SB];
__device__ int      g_bpre[SB];
__device__ float    g_dinv[N_];
__device__ int      g_flag;             // 1 = edge_index is int64, 0 = int32
__device__ float    g_als[N_ * 2];
__device__ float    g_ald[N_ * 2];
__device__ float    g_va[8 * 128];      // folded attention W@a (rows 0-3: L1, 4-7: L2)
__device__ __half   g_wt[640 * 128];    // all 4 transposed fp16 weights
__device__ __half   g_xh[N_ * 128];     // fp16 copy of input x
__device__ __half   g_bufAh[N_ * 256];  // GEMM outputs fp16
__device__ __half   g_bufCh[N_ * 128];  // activations fp16 (GEMM feed)

// weight row offsets in g_wt
#define WT_G1 0
#define WT_A1 (128 * 128)
#define WT_G2 (384 * 128)
#define WT_A2 (512 * 128)

// ---------------- helpers ---------------------------------------------------
__device__ __forceinline__ float lrelu(float e) { return e > 0.f ? e : 0.2f * e; }

__device__ __forceinline__ float wred_sum(float v) {
#pragma unroll
    for (int o = 16; o; o >>= 1) v += __shfl_xor_sync(0xffffffffu, v, o);
    return v;
}
__device__ __forceinline__ float gred_sum(float v, unsigned m) {
#pragma unroll
    for (int o = 8; o; o >>= 1) v += __shfl_xor_sync(m, v, o);
    return v;
}

__device__ __forceinline__ void ld8(float* v, const __half* p) {
    uint4 u = *(const uint4*)p;
    const __half2* h = (const __half2*)&u;
#pragma unroll
    for (int i = 0; i < 4; i++) {
        float2 f = __half22float2(h[i]);
        v[2 * i] = f.x; v[2 * i + 1] = f.y;
    }
}
__device__ __forceinline__ void st8h(__half* p, const float* v) {
    uint4 u;
    __half2* h = (__half2*)&u;
#pragma unroll
    for (int i = 0; i < 4; i++) h[i] = __floats2half2_rn(v[2 * i], v[2 * i + 1]);
    *(uint4*)p = u;
}
__device__ __forceinline__ uint2 f4_to_h4(float4 v) {
    __half2 h0 = __floats2half2_rn(v.x, v.y);
    __half2 h1 = __floats2half2_rn(v.z, v.w);
    uint2 u;
    u.x = *(unsigned*)&h0; u.y = *(unsigned*)&h1;
    return u;
}
__device__ __forceinline__ uint32_t smem_u32(const void* p) {
    return (uint32_t)__cvta_generic_to_shared(p);
}
__device__ __forceinline__ void ldm4(uint32_t& r0, uint32_t& r1, uint32_t& r2,
                                     uint32_t& r3, uint32_t addr) {
    asm volatile("ldmatrix.sync.aligned.m8n8.x4.shared.b16 {%0,%1,%2,%3}, [%4];"
                 : "=r"(r0), "=r"(r1), "=r"(r2), "=r"(r3) : "r"(addr));
}
__device__ __forceinline__ void mma16816(float* d, const uint32_t* a,
                                         uint32_t b0, uint32_t b1) {
    asm volatile(
        "mma.sync.aligned.m16n8k16.row.col.f32.f16.f16.f32 "
        "{%0,%1,%2,%3}, {%4,%5,%6,%7}, {%8,%9}, {%0,%1,%2,%3};"
        : "+f"(d[0]), "+f"(d[1]), "+f"(d[2]), "+f"(d[3])
        : "r"(a[0]), "r"(a[1]), "r"(a[2]), "r"(a[3]), "r"(b0), "r"(b1));
}
__device__ __forceinline__ void cpa16(uint32_t dst, const void* src, int sz) {
    asm volatile("cp.async.cg.shared.global [%0], [%1], 16, %2;"
                 :: "r"(dst), "l"(src), "r"(sz));
}
__device__ __forceinline__ void cpa_commit() {
    asm volatile("cp.async.commit_group;");
}
__device__ __forceinline__ void cpa_wait0() {
    asm volatile("cp.async.wait_group 0;");
}

// ---------------- preprocessing ---------------------------------------------
__global__ void k_prep_all(const void* eidx, const float* __restrict__ x,
                           __half* __restrict__ xh) {
    int i = blockIdx.x * 256 + threadIdx.x;
    if (i < N_) g_deg[i] = 0;
    if (i < N_ * 32) {
        float4 v = *(const float4*)(x + (size_t)i * 4);
        *(uint2*)(xh + (size_t)i * 4) = f4_to_h4(v);
    }
    if (i == 0) {
        const long long* p = (const long long*)eidx;
        int ok = 1;
        for (int j = 0; j < 128; j++) {
            long long v = p[j];
            if (v < 0 || v >= N_) { ok = 0; break; }
        }
        g_flag = ok;
    }
}

// degree count: reads ONLY the dst half of edge_index
__global__ void k_convert(const void* eidx) {
    int i = blockIdx.x * 256 + threadIdx.x;
    if (i >= E_) return;
    int d = g_flag ? (int)((const long long*)eidx)[E_ + i]
                   : ((const int*)eidx)[E_ + i];
    atomicAdd(&g_deg[d], 1);
}

__global__ void __launch_bounds__(256) k_scan1() {
    __shared__ int sh[256];
    int t = threadIdx.x, b = blockIdx.x;
    int i = b * NPB + t;
    sh[t] = (t < NPB) ? g_deg[i] : 0;
    __syncthreads();
    for (int off = 128; off; off >>= 1) {
        if (t < off) sh[t] += sh[t + off];
        __syncthreads();
    }
    if (t == 0) g_bsum[b] = sh[0];
}

__global__ void __launch_bounds__(256) k_scan2() {
    __shared__ int sh[256];
    int t = threadIdx.x;
    int v = (t < SB) ? g_bsum[t] : 0;
    sh[t] = v;
    __syncthreads();
    for (int off = 1; off < 256; off <<= 1) {
        int u = (t >= off) ? sh[t - off] : 0;
        __syncthreads();
        sh[t] += u;
        __syncthreads();
    }
    if (t < SB) g_bpre[t] = sh[t] - v;  // exclusive
}

__global__ void __launch_bounds__(256) k_scan3() {
    __shared__ int sh[256];
    int t = threadIdx.x, b = blockIdx.x;
    int i = b * NPB + t;
    int d = (t < NPB) ? g_deg[i] : 0;
    sh[t] = d;
    __syncthreads();
    for (int off = 1; off < 256; off <<= 1) {
        int u = (t >= off) ? sh[t - off] : 0;
        __syncthreads();
        sh[t] += u;
        __syncthreads();
    }
    if (t < NPB) {
        g_rowstart[i] = g_bpre[b] + sh[t] - d;
        g_dinv[i] = rsqrtf((float)(d + 1));  // +1 self loop
        g_fill[i] = 0;
    }
    if (b == SB - 1 && t == 0) g_rowstart[N_] = E_;
}

// CSR fill: reads edge_index directly (both halves)
__global__ void k_csr(const void* eidx) {
    int i = blockIdx.x * 256 + threadIdx.x;
    if (i >= E_) return;
    int s, d;
    if (g_flag) {
        const long long* p = (const long long*)eidx;
        s = (int)p[i]; d = (int)p[E_ + i];
    } else {
        const int* p = (const int*)eidx;
        s = p[i]; d = p[E_ + i];
    }
    int pos = g_rowstart[d] + atomicAdd(&g_fill[d], 1);
    g_esrc[pos] = s;
}

// ------- constants: weight transpose-convert + folded attention (1 kernel) --
__global__ void k_const(const float* __restrict__ Wg1, const float* __restrict__ Wa1,
                        const float* __restrict__ Wg2, const float* __restrict__ Wa2,
                        const float* __restrict__ as1, const float* __restrict__ ad1,
                        const float* __restrict__ as2, const float* __restrict__ ad2) {
    int b = blockIdx.x;
    if (b < 320) {
        int idx = b * 256 + threadIdx.x;
        int row = idx >> 7, k = idx & 127;
        const float* W; int co, n;
        if (row < 128)      { W = Wg1; co = 128; n = row; }
        else if (row < 384) { W = Wa1; co = 256; n = row - 128; }
        else if (row < 512) { W = Wg2; co = 128; n = row - 384; }
        else                { W = Wa2; co = 128; n = row - 512; }
        g_wt[idx] = __float2half(W[(size_t)k * co + n]);
    } else {
        int j = b - 320, k = threadIdx.x;
        if (k < 128) {
            const float* W; const float* a; int co, C;
            int jj = j & 3;
            if (j < 4) { W = Wa1; a = (jj < 2) ? as1 : ad1; co = 256; C = 128; }
            else       { W = Wa2; a = (jj < 2) ? as2 : ad2; co = 128; C = 64; }
            int h = jj & 1;
            float s = 0.f;
            for (int c = 0; c < C; c++) s += W[(size_t)k * co + h * C + c] * a[h * C + c];
            g_va[j * 128 + k] = s;
        }
    }
}

// ---- HMMA GEMM: BM=128; CO/64 halves, resident A, cp.async double-buffer B -
__global__ void __launch_bounds__(256) k_gemm_h(const __half* __restrict__ A,
                                                const __half* __restrict__ Wt,
                                                __half* __restrict__ Ch, int CO) {
    extern __shared__ __half dyn[];
    __half* As  = dyn;               // 128x128, row r: granule g at (g ^ (r&7))
    __half* Bs0 = dyn + 128 * 128;   // 64x128 double buffer
    __half* Bs1 = Bs0 + 64 * 128;
    const int bm = blockIdx.x * 128;
    const int tid = threadIdx.x;
    const int warp = tid >> 5, lane = tid & 31;

    // As via cp.async (zero-fill OOB rows)
    {
        int r = tid >> 1, hh = tid & 1;
        int gr = bm + r;
        const __half* src = A + (size_t)gr * 128 + hh * 64;
        int sz = (gr < N_) ? 16 : 0;
#pragma unroll
        for (int g = 0; g < 8; g++) {
            int gg = hh * 8 + g;
            cpa16(smem_u32(&As[r * 128 + ((gg ^ (r & 7)) << 3)]), src + g * 8, sz);
        }
    }
    // B half 0
    {
        int n = tid >> 2, q = tid & 3;
        const __half* src = Wt + (size_t)n * 128 + q * 32;
#pragma unroll
        for (int g = 0; g < 4; g++) {
            int gg = q * 4 + g;
            cpa16(smem_u32(&Bs0[n * 128 + ((gg ^ (n & 7)) << 3)]), src + g * 8, 16);
        }
    }
    cpa_commit();

    const uint32_t sA = smem_u32(As);
    const int wm = (warp & 3) * 32, wn = (warp >> 2) * 32;
    const int H = CO >> 6;

    for (int hb = 0; hb < H; hb++) {
        cpa_wait0();        // buffer hb complete
        __syncthreads();    // visible to all; all warps done reading buffer hb^1
        if (hb + 1 < H) {   // prefetch next half (overlaps this half's compute)
            __half* Bn = ((hb + 1) & 1) ? Bs1 : Bs0;
            int n = tid >> 2, q = tid & 3;
            const __half* src = Wt + (size_t)((hb + 1) * 64 + n) * 128 + q * 32;
#pragma unroll
            for (int g = 0; g < 4; g++) {
                int gg = q * 4 + g;
                cpa16(smem_u32(&Bn[n * 128 + ((gg ^ (n & 7)) << 3)]), src + g * 8, 16);
            }
            cpa_commit();
        }
        const uint32_t sB = smem_u32((hb & 1) ? Bs1 : Bs0);

        float acc[2][4][4];
#pragma unroll
        for (int mt = 0; mt < 2; mt++)
#pragma unroll
            for (int nt = 0; nt < 4; nt++)
#pragma unroll
                for (int i = 0; i < 4; i++) acc[mt][nt][i] = 0.f;

#pragma unroll
        for (int kk = 0; kk < 8; kk++) {
            uint32_t a[2][4];
#pragma unroll
            for (int mt = 0; mt < 2; mt++) {
                int r = wm + mt * 16 + (lane & 15);
                int kg = kk * 2 + (lane >> 4);
                ldm4(a[mt][0], a[mt][1], a[mt][2], a[mt][3],
                     sA + (uint32_t)(r * 128 + ((kg ^ (r & 7)) << 3)) * 2);
            }
            uint32_t b[2][4];
#pragma unroll
            for (int nt2 = 0; nt2 < 2; nt2++) {
                int n = wn + nt2 * 16 + (lane & 7) + ((lane >> 4) << 3);
                int kg = kk * 2 + ((lane >> 3) & 1);
                ldm4(b[nt2][0], b[nt2][1], b[nt2][2], b[nt2][3],
                     sB + (uint32_t)(n * 128 + ((kg ^ (n & 7)) << 3)) * 2);
            }
#pragma unroll
            for (int mt = 0; mt < 2; mt++)
#pragma unroll
                for (int nt = 0; nt < 4; nt++) {
                    int nt2 = nt >> 1, sub = nt & 1;
                    mma16816(acc[mt][nt], a[mt], b[nt2][sub * 2], b[nt2][sub * 2 + 1]);
                }
        }

        int bn = hb * 64;
#pragma unroll
        for (int mt = 0; mt < 2; mt++) {
            int r0 = bm + wm + mt * 16 + (lane >> 2);
#pragma unroll
            for (int half = 0; half < 2; half++) {
                int r = r0 + half * 8;
                if (r < N_) {
#pragma unroll
                    for (int nt = 0; nt < 4; nt++) {
                        int cc = bn + wn + nt * 8 + (lane & 3) * 2;
                        *(__half2*)(Ch + (size_t)r * CO + cc) =
                            __floats2half2_rn(acc[mt][nt][half * 2],
                                              acc[mt][nt][half * 2 + 1]);
                    }
                }
            }
        }
    }
}

// ------- GCN aggregate: 2 nodes/warp, 16B loads + BN + ReLU + GAT logits ----
__global__ void __launch_bounds__(256) k_gcn_gather(
    const __half* __restrict__ hh, __half* __restrict__ outh,
    const float* __restrict__ bias, const float* __restrict__ gamma,
    const float* __restrict__ beta, const float* __restrict__ mean,
    const float* __restrict__ var, int vaOff) {
    int gw = (blockIdx.x * 256 + threadIdx.x) >> 5;
    if (gw * 2 >= N_) return;
    int lane = threadIdx.x & 31;
    int g = lane >> 4, cl = lane & 15;
    int n = gw * 2 + g;
    unsigned gmask = 0xFFFFu << (g * 16);
    int cb = cl * 8;

    float din = g_dinv[n];
    float ws = din * din;
    float acc[8];
    ld8(acc, hh + (size_t)n * 128 + cb);
#pragma unroll
    for (int i = 0; i < 8; i++) acc[i] *= ws;

    int beg = g_rowstart[n];
    int deg = g_rowstart[n + 1] - beg;
    for (int base = 0; base < deg; base += 16) {
        int cnt = min(16, deg - base);
        int s = 0; float w = 0.f;
        if (cl < cnt) { s = g_esrc[beg + base + cl]; w = g_dinv[s] * din; }
        for (int j = 0; j < cnt; j++) {
            int sj = __shfl_sync(gmask, s, (g << 4) + j);
            float wj = __shfl_sync(gmask, w, (g << 4) + j);
            float v[8];
            ld8(v, hh + (size_t)sj * 128 + cb);
#pragma unroll
            for (int i = 0; i < 8; i++) acc[i] += wj * v[i];
        }
    }
    float o[8];
    float4 b0 = *(const float4*)(bias + cb),  b1 = *(const float4*)(bias + cb + 4);
    float4 gm0 = *(const float4*)(gamma + cb), gm1 = *(const float4*)(gamma + cb + 4);
    float4 bt0 = *(const float4*)(beta + cb),  bt1 = *(const float4*)(beta + cb + 4);
    float4 mn0 = *(const float4*)(mean + cb),  mn1 = *(const float4*)(mean + cb + 4);
    float4 vr0 = *(const float4*)(var + cb),   vr1 = *(const float4*)(var + cb + 4);
#pragma unroll
    for (int i = 0; i < 8; i++) {
        float bb = (i < 4) ? (&b0.x)[i] : (&b1.x)[i - 4];
        float gg = (i < 4) ? (&gm0.x)[i] : (&gm1.x)[i - 4];
        float tt = (i < 4) ? (&bt0.x)[i] : (&bt1.x)[i - 4];
        float mm = (i < 4) ? (&mn0.x)[i] : (&mn1.x)[i - 4];
        float vv = (i < 4) ? (&vr0.x)[i] : (&vr1.x)[i - 4];
        float val = acc[i] + bb;
        val = (val - mm) * rsqrtf(vv + 1e-5f) * gg + tt;
        o[i] = fmaxf(val, 0.f);
    }
    st8h(outh + (size_t)n * 128 + cb, o);

    float r[4];
#pragma unroll
    for (int j = 0; j < 4; j++) {
        const float* vap = g_va + (vaOff + j) * 128 + cb;
        float4 p0 = *(const float4*)vap, p1 = *(const float4*)(vap + 4);
        float s = o[0] * p0.x + o[1] * p0.y + o[2] * p0.z + o[3] * p0.w +
                  o[4] * p1.x + o[5] * p1.y + o[6] * p1.z + o[7] * p1.w;
        r[j] = gred_sum(s, gmask);
    }
    if (cl == 0) {
        g_als[n * 2 + 0] = r[0]; g_als[n * 2 + 1] = r[1];
        g_ald[n * 2 + 0] = r[2]; g_ald[n * 2 + 1] = r[3];
    }
}

// ------- GAT aggregate, C=128: 1 node/warp, 16B loads cover both heads ------
__global__ void __launch_bounds__(256) k_gat_gather128(
    const __half* __restrict__ hgh, __half* __restrict__ outh,
    const float* __restrict__ bias) {
    int n = (blockIdx.x * 256 + threadIdx.x) >> 5;
    if (n >= N_) return;
    int lane = threadIdx.x & 31;
    int h = lane >> 4;
    int cb = lane * 8;

    float ald0 = g_ald[n * 2], ald1 = g_ald[n * 2 + 1];
    float den0 = __expf(lrelu(g_als[n * 2] + ald0));
    float den1 = __expf(lrelu(g_als[n * 2 + 1] + ald1));
    float wself = h ? den1 : den0;

    float acc[8];
    ld8(acc, hgh + (size_t)n * 256 + cb);
#pragma unroll
    for (int i = 0; i < 8; i++) acc[i] *= wself;

    int beg = g_rowstart[n];
    int deg = g_rowstart[n + 1] - beg;
    for (int base = 0; base < deg; base += 32) {
        int cnt = min(32, deg - base);
        int s = 0; float w0 = 0.f, w1 = 0.f;
        if (lane < cnt) {
            s = g_esrc[beg + base + lane];
            float2 al = *(const float2*)&g_als[2 * s];
            w0 = __expf(lrelu(al.x + ald0));
            w1 = __expf(lrelu(al.y + ald1));
        }
        den0 += wred_sum(w0); den1 += wred_sum(w1);
        for (int j = 0; j < cnt; j++) {
            int sj = __shfl_sync(0xffffffffu, s, j);
            float w0j = __shfl_sync(0xffffffffu, w0, j);
            float w1j = __shfl_sync(0xffffffffu, w1, j);
            float wj = h ? w1j : w0j;
            float v[8];
            ld8(v, hgh + (size_t)sj * 256 + cb);
#pragma unroll
            for (int i = 0; i < 8; i++) acc[i] += wj * v[i];
        }
    }
    float r = 0.5f / (h ? den1 : den0);
    float o[8];
#pragma unroll
    for (int i = 0; i < 8; i++) {
        float val = acc[i] * r;
        o[i] = val + __shfl_xor_sync(0xffffffffu, val, 16);
    }
    if (lane < 16) {
        int oc = lane * 8;
        float4 b0 = *(const float4*)(bias + oc), b1 = *(const float4*)(bias + oc + 4);
#pragma unroll
        for (int i = 0; i < 8; i++) {
            float bb = (i < 4) ? (&b0.x)[i] : (&b1.x)[i - 4];
            o[i] = fmaxf(o[i] + bb, 0.f);
        }
        st8h(outh + (size_t)n * 128 + oc, o);
    }
}

// ------- GAT aggregate, C=64: 2 nodes/warp + bias + log_softmax -------------
__global__ void __launch_bounds__(256) k_gat_gather64(
    const __half* __restrict__ hgh,
    float* __restrict__ out, const float* __restrict__ bias) {
    int gw = (blockIdx.x * 256 + threadIdx.x) >> 5;
    if (gw * 2 >= N_) return;
    int lane = threadIdx.x & 31;
    int g = lane >> 4, cl = lane & 15;
    int n = gw * 2 + g;
    unsigned gmask = 0xFFFFu << (g * 16);
    int h = cl >> 3;
    int cb = (cl & 7) * 8;

    float ald0 = g_ald[n * 2], ald1 = g_ald[n * 2 + 1];
    float es0 = __expf(lrelu(g_als[n * 2] + ald0));
    float es1 = __expf(lrelu(g_als[n * 2 + 1] + ald1));
    float den = h ? es1 : es0;

    float acc[8];
    ld8(acc, hgh + (size_t)n * 128 + cl * 8);
#pragma unroll
    for (int i = 0; i < 8; i++) acc[i] *= den;

    int beg = g_rowstart[n];
    int deg = g_rowstart[n + 1] - beg;
    for (int base = 0; base < deg; base += 16) {
        int cnt = min(16, deg - base);
        int s = 0; float w0 = 0.f, w1 = 0.f;
        if (cl < cnt) {
            s = g_esrc[beg + base + cl];
            float2 al = *(const float2*)&g_als[2 * s];
            w0 = __expf(lrelu(al.x + ald0));
            w1 = __expf(lrelu(al.y + ald1));
        }
        float sw0 = gred_sum(w0, gmask), sw1 = gred_sum(w1, gmask);
        den += h ? sw1 : sw0;
        for (int j = 0; j < cnt; j++) {
            int sj = __shfl_sync(gmask, s, (g << 4) + j);
            float w0j = __shfl_sync(gmask, w0, (g << 4) + j);
            float w1j = __shfl_sync(gmask, w1, (g << 4) + j);
            float wj = h ? w1j : w0j;
            float v[8];
            ld8(v, hgh + (size_t)sj * 128 + cl * 8);
#pragma unroll
            for (int i = 0; i < 8; i++) acc[i] += wj * v[i];
        }
    }
    float inv = 1.f / den;
    float4 b0 = *(const float4*)(bias + cb), b1 = *(const float4*)(bias + cb + 4);
    float o[8];
#pragma unroll
    for (int i = 0; i < 8; i++) {
        float val = acc[i] * inv;
        float bb = (i < 4) ? (&b0.x)[i] : (&b1.x)[i - 4];
        o[i] = 0.5f * (val + __shfl_xor_sync(gmask, val, 8)) + bb;
    }
    float lm = o[0];
#pragma unroll
    for (int i = 1; i < 8; i++) lm = fmaxf(lm, o[i]);
#pragma unroll
    for (int off = 4; off; off >>= 1) lm = fmaxf(lm, __shfl_xor_sync(gmask, lm, off));
    float sum = 0.f;
#pragma unroll
    for (int i = 0; i < 8; i++) sum += __expf(o[i] - lm);
#pragma unroll
    for (int off = 4; off; off >>= 1) sum += __shfl_xor_sync(gmask, sum, off);
    float l = lm + logf(sum);
    if (h == 0) {
        float* op = out + (size_t)n * 64 + cb;
        *(float4*)op = make_float4(o[0] - l, o[1] - l, o[2] - l, o[3] - l);
        *(float4*)(op + 4) = make_float4(o[4] - l, o[5] - l, o[6] - l, o[7] - l);
    }
}

// ---------------- launch -----------------------------------------------------
extern "C" void kernel_launch(void* const* d_in, const int* in_sizes, int n_in,
                              void* d_out, int out_size) {
    const float* x   = (const float*)d_in[0];
    const void*  ei  = d_in[1];
    const float* Wg1 = (const float*)d_in[2];
    const float* bg1 = (const float*)d_in[3];
    const float* g1g = (const float*)d_in[4];
    const float* g1b = (const float*)d_in[5];
    const float* g1m = (const float*)d_in[6];
    const float* g1v = (const float*)d_in[7];
    const float* Wa1 = (const float*)d_in[8];
    const float* as1 = (const float*)d_in[9];
    const float* ad1 = (const float*)d_in[10];
    const float* ba1 = (const float*)d_in[11];
    const float* Wg2 = (const float*)d_in[12];
    const float* bg2 = (const float*)d_in[13];
    const float* g2g = (const float*)d_in[14];
    const float* g2b = (const float*)d_in[15];
    const float* g2m = (const float*)d_in[16];
    const float* g2v = (const float*)d_in[17];
    const float* Wa2 = (const float*)d_in[18];
    const float* as2 = (const float*)d_in[19];
    const float* ad2 = (const float*)d_in[20];
    const float* ba2 = (const float*)d_in[21];
    float* out = (float*)d_out;

    __half *bufAh, *bufCh, *wt, *xh;
    cudaGetSymbolAddress((void**)&bufAh, g_bufAh);
    cudaGetSymbolAddress((void**)&bufCh, g_bufCh);
    cudaGetSymbolAddress((void**)&wt, g_wt);
    cudaGetSymbolAddress((void**)&xh, g_xh);

    const int GEMM_SMEM = (128 * 128 + 2 * 64 * 128) * (int)sizeof(__half);  // 64 KB
    static int attr_done = 0;
    if (!attr_done) {
        cudaFuncSetAttribute(k_gemm_h, cudaFuncAttributeMaxDynamicSharedMemorySize,
                             GEMM_SMEM);
        attr_done = 1;
    }

    const int TB = 256;
    const int eb = (E_ + TB - 1) / TB;
    const int nw1 = (N_ * 32 + TB - 1) / TB;        // 1 node/warp grids
    const int nw2 = ((N_ / 2) * 32 + TB - 1) / TB;  // 2 nodes/warp grids
    const int GX = (N_ + 127) / 128;                // 391 GEMM row tiles

    // ---- preprocessing
    k_prep_all<<<(N_ * 32 + TB - 1) / TB, TB>>>(ei, x, xh);
    k_convert<<<eb, TB>>>(ei);
    k_scan1<<<SB, TB>>>();
    k_scan2<<<1, TB>>>();
    k_scan3<<<SB, TB>>>();
    k_csr<<<eb, TB>>>(ei);
    k_const<<<328, TB>>>(Wg1, Wa1, Wg2, Wa2, as1, ad1, as2, ad2);

    // ---- GCN1 (+ bias + BN1 + ReLU + GAT1 logits)
    k_gemm_h<<<GX, TB, GEMM_SMEM>>>(xh, wt + WT_G1, bufAh, 128);
    k_gcn_gather<<<nw2, TB>>>(bufAh, bufCh, bg1, g1g, g1b, g1m, g1v, 0);

    // ---- GAT1 (single-pass softmax + head-mean + bias + ReLU)
    k_gemm_h<<<GX, TB, GEMM_SMEM>>>(bufCh, wt + WT_A1, bufAh, 256);
    k_gat_gather128<<<nw1, TB>>>(bufAh, bufCh, ba1);

    // ---- GCN2 (+ bias + BN2 + ReLU + GAT2 logits)
    k_gemm_h<<<GX, TB, GEMM_SMEM>>>(bufCh, wt + WT_G2, bufAh, 128);
    k_gcn_gather<<<nw2, TB>>>(bufAh, bufCh, bg2, g2g, g2b, g2m, g2v, 4);

    // ---- GAT2 (single-pass softmax + head-mean + bias + log_softmax)
    k_gemm_h<<<GX, TB, GEMM_SMEM>>>(bufCh, wt + WT_A2, bufAh, 128);
    k_gat_gather64<<<nw2, TB>>>(bufAh, out, ba2);
}